// round 11
// baseline (speedup 1.0000x reference)
#include <cuda_runtime.h>
#include <cuda_fp16.h>
#include <cstdint>

// Problem constants
#define N_NODES 100000
#define N_EDGES 400000
#define DIM     128
#define KDIM    384       // 3*DIM
#define HID     768       // 6*DIM
#define TILE_M  64
#define N_TILES (N_EDGES / TILE_M)   // 6250
#define KTILES  24                   // 384 / 16
#define N_QTRS  24                   // 6 steps x 4 quarters

// W1 fp16, m16n8k16 B-fragment order, grouped for quarter-step cp.async:
// [step 6][quarter 4][ntile 16][kt6][lane 32][8B]   (24 KB per quarter)
__device__ __align__(16) __half g_w1frag[HID * KDIM];

static constexpr uint32_t B_STEP_BYTES = 16 * 24 * 32 * 8;   // 98304
static constexpr uint32_t B_QTR_BYTES  = B_STEP_BYTES / 4;   // 24576

// ---------------- SMEM layout (per CTA: 105472 B -> 2 CTAs/SM) ----------------
// A (feat fragments, 64 rows): [mtile 4][ktile 24][lane 32][16B] = 49152
static constexpr int SM_A    = 0;
static constexpr int SM_B    = 49152;    // 2 x 24576 quarter double-buffer
static constexpr int SM_W2   = 98304;    // 768 f32
static constexpr int SM_B1   = 101376;   // 768 f32
static constexpr int SM_PART = 104448;   // 4 x 64 f32
static constexpr int SMEM_TOTAL = 105472;

// ---------------- helpers ----------------
__device__ __forceinline__ uint32_t smem_u32(const void* p) {
    uint32_t a;
    asm("{ .reg .u64 t; cvta.to.shared.u64 t, %1; cvt.u32.u64 %0, t; }" : "=r"(a) : "l"(p));
    return a;
}
__device__ __forceinline__ void cp16(uint32_t dst, const void* src) {
    asm volatile("cp.async.cg.shared.global [%0], [%1], 16;" :: "r"(dst), "l"(src) : "memory");
}
__device__ __forceinline__ void cp_commit() {
    asm volatile("cp.async.commit_group;" ::: "memory");
}
template <int N>
__device__ __forceinline__ void cp_wait() {
    asm volatile("cp.async.wait_group %0;" :: "n"(N) : "memory");
}
__device__ __forceinline__ void mma16816(float* d, const uint32_t* a, const uint32_t* b) {
    asm volatile(
        "mma.sync.aligned.m16n8k16.row.col.f32.f16.f16.f32 "
        "{%0,%1,%2,%3}, {%4,%5,%6,%7}, {%8,%9}, {%0,%1,%2,%3};"
        : "+f"(d[0]), "+f"(d[1]), "+f"(d[2]), "+f"(d[3])
        : "r"(a[0]), "r"(a[1]), "r"(a[2]), "r"(a[3]), "r"(b[0]), "r"(b[1]));
}

// A-fragment smem byte offset for (row r in 0..63, kpair p in 0..191)
__device__ __forceinline__ uint32_t a_frag_off(int r, int p) {
    int kt   = p >> 3;
    int kp   = p & 7;
    int ln   = ((r & 7) << 2) + (kp & 3);
    int word = ((r >> 3) & 1) + ((kp >> 2) << 1);
    int mt   = r >> 4;            // 0..3
    return (uint32_t)(((mt * KTILES + kt) << 9) + (ln << 4) + (word << 2));
}

// ---------------- prep: W1 fp32 -> fp16 fragment-ordered (quarter grouping) ----------------
__global__ void prep_w1_kernel(const float* __restrict__ W1) {
    int i = blockIdx.x * blockDim.x + threadIdx.x;
    if (i >= HID * KDIM) return;
    int n = i / KDIM;
    int k = i - n * KDIM;
    int step = n >> 7;            // 128 cols per step
    int np   = n & 127;
    int nt   = np >> 3;           // 16 ntiles per step
    int g    = np & 7;
    int kt   = k >> 4;            // 0..23
    int qtr  = kt / 6;
    int kt6  = kt - qtr * 6;
    int kk   = k & 15;
    int w    = kk >> 3;
    int t    = (kk & 7) >> 1;
    int hb   = kk & 1;
    uint32_t off = (uint32_t)step * B_STEP_BYTES + (uint32_t)qtr * B_QTR_BYTES
                 + (uint32_t)((nt * 6 + kt6) << 8)
                 + (uint32_t)(((g << 2) + t) << 3) + (uint32_t)(w << 2) + (uint32_t)(hb << 1);
    *(__half*)((char*)g_w1frag + off) = __float2half_rn(W1[i]);
}

// ---------------- main fused kernel ----------------
__global__ void __launch_bounds__(256, 2) edge_mlp_hmma(
    const float* __restrict__ x,
    const int* __restrict__ ei,     // int32 (JAX x64 disabled)
    const float* __restrict__ b1g,
    const float* __restrict__ w2g,
    const float* __restrict__ b2g,
    float* __restrict__ out)
{
    extern __shared__ char smem[];
    const uint32_t sb = smem_u32(smem);
    const int tid  = threadIdx.x;
    const int lane = tid & 31;
    const int wid  = tid >> 5;
    const int mg   = wid & 1;      // 2 m-groups (32 rows = 2 mtiles each)
    const int ng   = wid >> 1;     // 4 n-groups (32 cols per step each)
    const int e0   = blockIdx.x * TILE_M;

    // prologue: cp.async quarters 0,1 (one commit group each)
    {
        const char* g0 = (const char*)g_w1frag + (uint32_t)tid * 16u;
#pragma unroll
        for (int j = 0; j < 6; j++)
            cp16(sb + SM_B + tid * 16 + j * 4096, g0 + j * 4096);
        cp_commit();
#pragma unroll
        for (int j = 0; j < 6; j++)
            cp16(sb + SM_B + B_QTR_BYTES + tid * 16 + j * 4096, g0 + B_QTR_BYTES + j * 4096);
        cp_commit();
    }

    // stage w2 / b1
    float* w2s = (float*)(smem + SM_W2);
    float* b1s = (float*)(smem + SM_B1);
#pragma unroll
    for (int i = 0; i < 3; i++) { w2s[tid + i * 256] = w2g[tid + i * 256];
                                  b1s[tid + i * 256] = b1g[tid + i * 256]; }

    // ---- build feat tile (64 rows) into smem A-fragment layout ----
    // 4 threads per row; each handles 8 float4s. kpair bases: mean 0, prod 64, sqdiff 128.
    {
        const int r  = tid & 63;
        const int qb = (tid >> 6) * 8;
        const int i0 = ei[e0 + r];
        const int i1 = ei[N_EDGES + e0 + r];
        const float4* p0 = (const float4*)x + (size_t)i0 * 32 + qb;
        const float4* p1 = (const float4*)x + (size_t)i1 * 32 + qb;
        char* As = smem + SM_A;
#pragma unroll
        for (int q = 0; q < 8; q++) {
            float4 a = p0[q];
            float4 c = p1[q];
            int qg = qb + q;
            __half2 h;
            h = __floats2half2_rn((a.x + c.x) * 0.5f, (a.y + c.y) * 0.5f);
            *(uint32_t*)(As + a_frag_off(r, 2 * qg))          = *(uint32_t*)&h;
            h = __floats2half2_rn((a.z + c.z) * 0.5f, (a.w + c.w) * 0.5f);
            *(uint32_t*)(As + a_frag_off(r, 2 * qg + 1))      = *(uint32_t*)&h;
            h = __floats2half2_rn(a.x * c.x, a.y * c.y);
            *(uint32_t*)(As + a_frag_off(r, 64 + 2 * qg))     = *(uint32_t*)&h;
            h = __floats2half2_rn(a.z * c.z, a.w * c.w);
            *(uint32_t*)(As + a_frag_off(r, 64 + 2 * qg + 1)) = *(uint32_t*)&h;
            float d0 = a.x - c.x, d1 = a.y - c.y, d2 = a.z - c.z, d3 = a.w - c.w;
            h = __floats2half2_rn(d0 * d0, d1 * d1);
            *(uint32_t*)(As + a_frag_off(r, 128 + 2 * qg))     = *(uint32_t*)&h;
            h = __floats2half2_rn(d2 * d2, d3 * d3);
            *(uint32_t*)(As + a_frag_off(r, 128 + 2 * qg + 1)) = *(uint32_t*)&h;
        }
    }

    // per-lane row accumulators: [mt0 g, mt0 g+8, mt1 g, mt1 g+8]
    float accv[4] = {0.f, 0.f, 0.f, 0.f};
    const int t4 = lane & 3;

    const uint32_t a_base = (uint32_t)SM_A + (uint32_t)(mg * 2 * KTILES) * 512u + (uint32_t)lane * 16u;
    const uint32_t b_rel  = (uint32_t)(ng * 4 * 6) * 256u + (uint32_t)lane * 8u;

    float C[8][4];

#pragma unroll 1
    for (int qi = 0; qi < N_QTRS; qi++) {
        const int qs = qi & 3;          // quarter within step
        if (qs == 0) {
#pragma unroll
            for (int f = 0; f < 8; f++)
#pragma unroll
                for (int v = 0; v < 4; v++) C[f][v] = 0.f;
        }

        cp_wait<1>();       // quarter qi resident in buffer qi&1
        __syncthreads();    // (also orders A-build on qi==0)

        const uint32_t bbuf = (uint32_t)SM_B + (uint32_t)(qi & 1) * B_QTR_BYTES + b_rel;
        const int ktb = qs * 6;   // global kt base within the step for A
#pragma unroll
        for (int kt = 0; kt < 6; kt++) {
            uint4 A0 = *(const uint4*)(smem + a_base + (uint32_t)(0 * KTILES + ktb + kt) * 512u);
            uint4 A1 = *(const uint4*)(smem + a_base + (uint32_t)(1 * KTILES + ktb + kt) * 512u);
            uint2 B0 = *(const uint2*)(smem + bbuf + (uint32_t)(0 * 6 + kt) * 256u);
            uint2 B1 = *(const uint2*)(smem + bbuf + (uint32_t)(1 * 6 + kt) * 256u);
            uint2 B2 = *(const uint2*)(smem + bbuf + (uint32_t)(2 * 6 + kt) * 256u);
            uint2 B3 = *(const uint2*)(smem + bbuf + (uint32_t)(3 * 6 + kt) * 256u);
            mma16816(C[0], (const uint32_t*)&A0, (const uint32_t*)&B0);
            mma16816(C[1], (const uint32_t*)&A0, (const uint32_t*)&B1);
            mma16816(C[2], (const uint32_t*)&A0, (const uint32_t*)&B2);
            mma16816(C[3], (const uint32_t*)&A0, (const uint32_t*)&B3);
            mma16816(C[4], (const uint32_t*)&A1, (const uint32_t*)&B0);
            mma16816(C[5], (const uint32_t*)&A1, (const uint32_t*)&B1);
            mma16816(C[6], (const uint32_t*)&A1, (const uint32_t*)&B2);
            mma16816(C[7], (const uint32_t*)&A1, (const uint32_t*)&B3);
        }
        __syncthreads();    // all warps done with buffer qi&1

        // refill buffer qi&1 with quarter qi+2 (keeps rolling group bookkeeping)
        if (qi + 2 < N_QTRS) {
            const char* src = (const char*)g_w1frag
                            + (uint32_t)(qi + 2) * B_QTR_BYTES + (uint32_t)tid * 16u;
            uint32_t d = sb + SM_B + (uint32_t)(qi & 1) * B_QTR_BYTES + tid * 16;
#pragma unroll
            for (int j = 0; j < 6; j++)
                cp16(d + j * 4096, src + j * 4096);
        }
        cp_commit();

        // fold relu(. + b1) * w2 at the end of each step
        if (qs == 3) {
            const int s = qi >> 2;
            const int nb = s * 128 + ng * 32 + t4 * 2;
#pragma unroll
            for (int bt = 0; bt < 4; bt++) {
                const int c0 = nb + bt * 8;
                float2 bb = *(const float2*)&b1s[c0];
                float2 ww = *(const float2*)&w2s[c0];
#pragma unroll
                for (int mt = 0; mt < 2; mt++) {
                    float* d = C[mt * 4 + bt];
                    accv[mt * 2 + 0] += fmaxf(d[0] + bb.x, 0.f) * ww.x
                                     + fmaxf(d[1] + bb.y, 0.f) * ww.y;
                    accv[mt * 2 + 1] += fmaxf(d[2] + bb.x, 0.f) * ww.x
                                     + fmaxf(d[3] + bb.y, 0.f) * ww.y;
                }
            }
        }
    }

    // reduce the 4 lanes sharing a g-group
#pragma unroll
    for (int i = 0; i < 4; i++) {
        accv[i] += __shfl_xor_sync(0xffffffffu, accv[i], 1);
        accv[i] += __shfl_xor_sync(0xffffffffu, accv[i], 2);
    }

    float* part = (float*)(smem + SM_PART);
    if (t4 == 0) {
        const int g = lane >> 2;
#pragma unroll
        for (int mt = 0; mt < 2; mt++) {
            const int row = mg * 32 + mt * 16 + g;
            part[ng * 64 + row]     = accv[mt * 2 + 0];
            part[ng * 64 + row + 8] = accv[mt * 2 + 1];
        }
    }
    __syncthreads();
    if (tid < 64)
        out[e0 + tid] = part[tid] + part[64 + tid] + part[128 + tid] + part[192 + tid] + b2g[0];
}

// ---------------- launch ----------------
extern "C" void kernel_launch(void* const* d_in, const int* in_sizes, int n_in,
                              void* d_out, int out_size) {
    const float* x  = (const float*)d_in[0];
    const int*   ei = (const int*)d_in[1];   // int32 (JAX default: x64 disabled)
    // d_in[2] edge_attr3, d_in[3] edge_attr4, d_in[4] batch: unused by reference
    const float* W1 = (const float*)d_in[5];
    const float* b1 = (const float*)d_in[6];
    const float* W2 = (const float*)d_in[7];
    const float* b2 = (const float*)d_in[8];
    float* out = (float*)d_out;

    prep_w1_kernel<<<(HID * KDIM + 255) / 256, 256>>>(W1);

    cudaFuncSetAttribute(edge_mlp_hmma,
                         cudaFuncAttributeMaxDynamicSharedMemorySize, SMEM_TOTAL);
    edge_mlp_hmma<<<N_TILES, 256, SMEM_TOTAL>>>(x, ei, b1, W2, b2, out);
}